// round 2
// baseline (speedup 1.0000x reference)
#include <cuda_runtime.h>

#define N_NODES   100000
#define N_EDGES   1600000
#define EDGE_FEAT 16
#define EDGE_HID  32
#define NODE_FEAT 128
#define TM 96
#define KC 16

// Scratch (allocation-free rule: __device__ globals)
__device__ float g_wsum[N_NODES * EDGE_FEAT];  // sum over edges of ex * feats
__device__ float g_ssum[N_NODES];              // sum over edges of ex
__device__ float g_ctx [N_NODES * EDGE_HID];   // elu(c) per node

// ---------------------------------------------------------------- zero scratch
__global__ void zero_kernel() {
    int i = blockIdx.x * blockDim.x + threadIdx.x;
    int stride = gridDim.x * blockDim.x;
    float4 z = make_float4(0.f, 0.f, 0.f, 0.f);
    float4* a = reinterpret_cast<float4*>(g_wsum);
    for (int idx = i; idx < N_NODES * EDGE_FEAT / 4; idx += stride) a[idx] = z;
    float4* b = reinterpret_cast<float4*>(g_ssum);
    for (int idx = i; idx < N_NODES / 4; idx += stride) b[idx] = z;
}

// ------------------------------------------------- edge pass: scatter ex, ex*f
// 4 threads per edge -> fully coalesced 512B/8-edges feature reads,
// vector reductions (red.v4) to L2-resident accumulators.
__global__ void edge_kernel(const float* __restrict__ logits,
                            const float4* __restrict__ feats4,
                            const int* __restrict__ dst) {
    int t = blockIdx.x * blockDim.x + threadIdx.x;
    int e = t >> 2;
    int q = t & 3;
    if (e >= N_EDGES) return;
    int d = dst[e];
    float ex = __expf(logits[e]);
    float4 f = feats4[e * 4 + q];
    f.x *= ex; f.y *= ex; f.z *= ex; f.w *= ex;
    float* p = g_wsum + d * EDGE_FEAT + q * 4;
    asm volatile("red.global.add.v4.f32 [%0], {%1,%2,%3,%4};"
                 :: "l"(p), "f"(f.x), "f"(f.y), "f"(f.z), "f"(f.w) : "memory");
    if (q == 0)
        asm volatile("red.global.add.f32 [%0], %1;"
                     :: "l"(g_ssum + d), "f"(ex) : "memory");
}

// --------------------------------- per-node: normalize, 16->32 GEMM, bias, elu
__global__ void ctx_kernel(const float* __restrict__ W_et,
                           const float* __restrict__ b_et) {
    __shared__ float Ws[EDGE_FEAT * EDGE_HID];
    __shared__ float bs[EDGE_HID];
    for (int i = threadIdx.x; i < EDGE_FEAT * EDGE_HID; i += blockDim.x) Ws[i] = W_et[i];
    if (threadIdx.x < EDGE_HID) bs[threadIdx.x] = b_et[threadIdx.x];
    __syncthreads();
    int n = blockIdx.x * blockDim.x + threadIdx.x;
    if (n >= N_NODES) return;
    float s = g_ssum[n];
    float inv = (s > 0.f) ? (1.f / s) : 0.f;   // denom==0 guard (empty segment)
    float ind = (s > 0.f) ? 1.f : 0.f;         // sum of alpha over segment
    float gv[EDGE_FEAT];
    const float4* gp = reinterpret_cast<const float4*>(g_wsum + n * EDGE_FEAT);
#pragma unroll
    for (int k4 = 0; k4 < 4; k4++) {
        float4 v = gp[k4];
        gv[k4 * 4 + 0] = v.x * inv; gv[k4 * 4 + 1] = v.y * inv;
        gv[k4 * 4 + 2] = v.z * inv; gv[k4 * 4 + 3] = v.w * inv;
    }
    float c[EDGE_HID];
#pragma unroll
    for (int j = 0; j < EDGE_HID; j++) c[j] = ind * bs[j];
#pragma unroll
    for (int k = 0; k < EDGE_FEAT; k++) {
        float a = gv[k];
#pragma unroll
        for (int j = 0; j < EDGE_HID; j++) c[j] = fmaf(a, Ws[k * EDGE_HID + j], c[j]);
    }
    float4* outp = reinterpret_cast<float4*>(g_ctx + n * EDGE_HID);
#pragma unroll
    for (int j4 = 0; j4 < 8; j4++) {
        float4 v;
        float x;
        x = c[j4 * 4 + 0]; v.x = (x > 0.f) ? x : expm1f(x);
        x = c[j4 * 4 + 1]; v.y = (x > 0.f) ? x : expm1f(x);
        x = c[j4 * 4 + 2]; v.z = (x > 0.f) ? x : expm1f(x);
        x = c[j4 * 4 + 3]; v.w = (x > 0.f) ? x : expm1f(x);
        outp[j4] = v;
    }
}

// --------------------- fused MLP: relu([ctx|nf] @ W1 + b1) @ W2 + b2, relu
// Block: 256 threads, tile 96 nodes x 128 outputs, 6x8 microtile.
// W1 (80KB) + W2 (64KB) + A-chunk + H-tile all in smem (~202KB), 1 block/SM.
__global__ __launch_bounds__(256, 1)
void mlp_kernel(const float4* __restrict__ nf4,
                const float* __restrict__ W1, const float* __restrict__ b1,
                const float* __restrict__ W2, const float* __restrict__ b2,
                float* __restrict__ out) {
    extern __shared__ float sm[];
    float* W1s = sm;                         // 160*128 = 20480 floats
    float* W2s = W1s + 160 * 128;            // 128*128 = 16384
    float* As  = W2s + 128 * 128;            // 96*20   = 1920 (stride 20, 16B-aligned rows, no bank conflict)
    float* Hs  = As + TM * 20;               // 96*132  = 12672 (stride 132 kills 2-way conflicts)
    float* b1s = Hs + TM * 132;              // 128
    float* b2s = b1s + 128;                  // 128   -> total 51712 floats = 206848 B

    const int tid = threadIdx.x;
    const int tx = tid & 15;                 // output-col group
    const int ty = tid >> 4;                 // node-row group
    const int node0 = blockIdx.x * TM;

    {   // cooperative weight staging
        const float4* w1v = reinterpret_cast<const float4*>(W1);
        float4* s1 = reinterpret_cast<float4*>(W1s);
#pragma unroll
        for (int i = 0; i < 20; i++) s1[tid + i * 256] = w1v[tid + i * 256];
        const float4* w2v = reinterpret_cast<const float4*>(W2);
        float4* s2 = reinterpret_cast<float4*>(W2s);
#pragma unroll
        for (int i = 0; i < 16; i++) s2[tid + i * 256] = w2v[tid + i * 256];
        if (tid < 128) { b1s[tid] = b1[tid]; b2s[tid] = b2[tid]; }
    }

    float acc[6][8];
#pragma unroll
    for (int i = 0; i < 6; i++)
#pragma unroll
        for (int j = 0; j < 8; j++) acc[i][j] = 0.f;

    const float4* ctx4 = reinterpret_cast<const float4*>(g_ctx);

    for (int kc = 0; kc < 10; kc++) {        // K = 160 = 10 chunks of 16
        __syncthreads();                     // As reuse fence (also covers weight staging on kc=0)
#pragma unroll
        for (int r = 0; r < 2; r++) {        // 384 float4 loads by 256 threads
            int i = tid + r * 256;
            if (i < TM * 4) {
                int m = i >> 2, q = i & 3;
                int node = node0 + m;
                if (node >= N_NODES) node = N_NODES - 1;   // clamp loads; stores guarded
                int k = kc * KC + q * 4;
                float4 v = (k < EDGE_HID) ? ctx4[node * 8 + (k >> 2)]
                                          : nf4[node * 32 + ((k - EDGE_HID) >> 2)];
                reinterpret_cast<float4*>(As)[m * 5 + q] = v;
            }
        }
        __syncthreads();
#pragma unroll
        for (int kk = 0; kk < KC; kk++) {
            int kg = kc * KC + kk;
            float a[6];
#pragma unroll
            for (int i = 0; i < 6; i++) a[i] = As[(ty * 6 + i) * 20 + kk];
            float4 bl = *reinterpret_cast<const float4*>(&W1s[kg * 128 + tx * 8]);
            float4 bh = *reinterpret_cast<const float4*>(&W1s[kg * 128 + tx * 8 + 4]);
            float b[8] = {bl.x, bl.y, bl.z, bl.w, bh.x, bh.y, bh.z, bh.w};
#pragma unroll
            for (int i = 0; i < 6; i++)
#pragma unroll
                for (int j = 0; j < 8; j++) acc[i][j] = fmaf(a[i], b[j], acc[i][j]);
        }
    }

    // epilogue 1: bias + relu -> Hs[node][col] (fully vectorized STS.128)
    {
        float bb[8];
#pragma unroll
        for (int j = 0; j < 8; j++) bb[j] = b1s[tx * 8 + j];
#pragma unroll
        for (int i = 0; i < 6; i++) {
            float4 v0, v1;
            v0.x = fmaxf(acc[i][0] + bb[0], 0.f);
            v0.y = fmaxf(acc[i][1] + bb[1], 0.f);
            v0.z = fmaxf(acc[i][2] + bb[2], 0.f);
            v0.w = fmaxf(acc[i][3] + bb[3], 0.f);
            v1.x = fmaxf(acc[i][4] + bb[4], 0.f);
            v1.y = fmaxf(acc[i][5] + bb[5], 0.f);
            v1.z = fmaxf(acc[i][6] + bb[6], 0.f);
            v1.w = fmaxf(acc[i][7] + bb[7], 0.f);
            float* hp = &Hs[(ty * 6 + i) * 132 + tx * 8];
            reinterpret_cast<float4*>(hp)[0] = v0;
            reinterpret_cast<float4*>(hp)[1] = v1;
        }
    }
    __syncthreads();

    // GEMM2: out = relu(H @ W2 + b2), reuse accumulators
#pragma unroll
    for (int i = 0; i < 6; i++)
#pragma unroll
        for (int j = 0; j < 8; j++) acc[i][j] = 0.f;

#pragma unroll 4
    for (int k = 0; k < 128; k++) {
        float a[6];
#pragma unroll
        for (int i = 0; i < 6; i++) a[i] = Hs[(ty * 6 + i) * 132 + k];
        float4 bl = *reinterpret_cast<const float4*>(&W2s[k * 128 + tx * 8]);
        float4 bh = *reinterpret_cast<const float4*>(&W2s[k * 128 + tx * 8 + 4]);
        float b[8] = {bl.x, bl.y, bl.z, bl.w, bh.x, bh.y, bh.z, bh.w};
#pragma unroll
        for (int i = 0; i < 6; i++)
#pragma unroll
            for (int j = 0; j < 8; j++) acc[i][j] = fmaf(a[i], b[j], acc[i][j]);
    }

    {
        float bb[8];
#pragma unroll
        for (int j = 0; j < 8; j++) bb[j] = b2s[tx * 8 + j];
        int rem = N_NODES - node0;
#pragma unroll
        for (int i = 0; i < 6; i++) {
            int m = ty * 6 + i;
            if (m < rem) {
                float4 v0, v1;
                v0.x = fmaxf(acc[i][0] + bb[0], 0.f);
                v0.y = fmaxf(acc[i][1] + bb[1], 0.f);
                v0.z = fmaxf(acc[i][2] + bb[2], 0.f);
                v0.w = fmaxf(acc[i][3] + bb[3], 0.f);
                v1.x = fmaxf(acc[i][4] + bb[4], 0.f);
                v1.y = fmaxf(acc[i][5] + bb[5], 0.f);
                v1.z = fmaxf(acc[i][6] + bb[6], 0.f);
                v1.w = fmaxf(acc[i][7] + bb[7], 0.f);
                float* op = out + (node0 + m) * 128 + tx * 8;
                reinterpret_cast<float4*>(op)[0] = v0;
                reinterpret_cast<float4*>(op)[1] = v1;
            }
        }
    }
}

extern "C" void kernel_launch(void* const* d_in, const int* in_sizes, int n_in,
                              void* d_out, int out_size) {
    const float* edge_logits = (const float*)d_in[0];
    const float* edge_feats  = (const float*)d_in[1];
    const float* node_feats  = (const float*)d_in[2];
    const int*   dst         = (const int*)d_in[3];
    const float* W_et        = (const float*)d_in[4];
    const float* b_et        = (const float*)d_in[5];
    const float* W1          = (const float*)d_in[6];
    const float* b1          = (const float*)d_in[7];
    const float* W2          = (const float*)d_in[8];
    const float* b2          = (const float*)d_in[9];
    float* out = (float*)d_out;

    cudaFuncSetAttribute(mlp_kernel, cudaFuncAttributeMaxDynamicSharedMemorySize, 206848);

    zero_kernel<<<1024, 256>>>();
    edge_kernel<<<(N_EDGES * 4) / 256, 256>>>(edge_logits,
                                              (const float4*)edge_feats, dst);
    ctx_kernel<<<(N_NODES + 255) / 256, 256>>>(W_et, b_et);
    mlp_kernel<<<(N_NODES + TM - 1) / TM, 256, 206848>>>(
        (const float4*)node_feats, W1, b1, W2, b2, out);
    (void)in_sizes; (void)n_in; (void)out_size;
}

// round 3
// speedup vs baseline: 1.1110x; 1.1110x over previous
#include <cuda_runtime.h>

#define N_NODES   100000
#define N_EDGES   1600000
#define EDGE_FEAT 16
#define EDGE_HID  32
#define NODE_FEAT 128
#define TM 128
#define KC 16

// Scratch (allocation-free rule: __device__ globals)
__device__ float g_wsum[N_NODES * EDGE_FEAT];  // sum over edges of ex * feats
__device__ float g_ssum[N_NODES];              // sum over edges of ex
__device__ float g_ctx [N_NODES * EDGE_HID];   // elu(c) per node

// ---------------------------------------------------------------- zero scratch
__global__ void zero_kernel() {
    int i = blockIdx.x * blockDim.x + threadIdx.x;
    int stride = gridDim.x * blockDim.x;
    float4 z = make_float4(0.f, 0.f, 0.f, 0.f);
    float4* a = reinterpret_cast<float4*>(g_wsum);
    for (int idx = i; idx < N_NODES * EDGE_FEAT / 4; idx += stride) a[idx] = z;
    float4* b = reinterpret_cast<float4*>(g_ssum);
    for (int idx = i; idx < N_NODES / 4; idx += stride) b[idx] = z;
}

// ------------------------------------------------- edge pass: scatter ex, ex*f
__global__ void edge_kernel(const float* __restrict__ logits,
                            const float4* __restrict__ feats4,
                            const int* __restrict__ dst) {
    int t = blockIdx.x * blockDim.x + threadIdx.x;
    int e = t >> 2;
    int q = t & 3;
    if (e >= N_EDGES) return;
    int d = dst[e];
    float ex = __expf(logits[e]);
    float4 f = feats4[e * 4 + q];
    f.x *= ex; f.y *= ex; f.z *= ex; f.w *= ex;
    float* p = g_wsum + d * EDGE_FEAT + q * 4;
    asm volatile("red.global.add.v4.f32 [%0], {%1,%2,%3,%4};"
                 :: "l"(p), "f"(f.x), "f"(f.y), "f"(f.z), "f"(f.w) : "memory");
    if (q == 0)
        asm volatile("red.global.add.f32 [%0], %1;"
                     :: "l"(g_ssum + d), "f"(ex) : "memory");
}

// --------------------------------- per-node: normalize, 16->32 GEMM, bias, elu
__global__ void ctx_kernel(const float* __restrict__ W_et,
                           const float* __restrict__ b_et) {
    __shared__ float Ws[EDGE_FEAT * EDGE_HID];
    __shared__ float bs[EDGE_HID];
    for (int i = threadIdx.x; i < EDGE_FEAT * EDGE_HID; i += blockDim.x) Ws[i] = W_et[i];
    if (threadIdx.x < EDGE_HID) bs[threadIdx.x] = b_et[threadIdx.x];
    __syncthreads();
    int n = blockIdx.x * blockDim.x + threadIdx.x;
    if (n >= N_NODES) return;
    float s = g_ssum[n];
    float inv = (s > 0.f) ? (1.f / s) : 0.f;
    float ind = (s > 0.f) ? 1.f : 0.f;
    float gv[EDGE_FEAT];
    const float4* gp = reinterpret_cast<const float4*>(g_wsum + n * EDGE_FEAT);
#pragma unroll
    for (int k4 = 0; k4 < 4; k4++) {
        float4 v = gp[k4];
        gv[k4 * 4 + 0] = v.x * inv; gv[k4 * 4 + 1] = v.y * inv;
        gv[k4 * 4 + 2] = v.z * inv; gv[k4 * 4 + 3] = v.w * inv;
    }
    float c[EDGE_HID];
#pragma unroll
    for (int j = 0; j < EDGE_HID; j++) c[j] = ind * bs[j];
#pragma unroll
    for (int k = 0; k < EDGE_FEAT; k++) {
        float a = gv[k];
#pragma unroll
        for (int j = 0; j < EDGE_HID; j++) c[j] = fmaf(a, Ws[k * EDGE_HID + j], c[j]);
    }
    float4* outp = reinterpret_cast<float4*>(g_ctx + n * EDGE_HID);
#pragma unroll
    for (int j4 = 0; j4 < 8; j4++) {
        float4 v;
        float x;
        x = c[j4 * 4 + 0]; v.x = (x > 0.f) ? x : expm1f(x);
        x = c[j4 * 4 + 1]; v.y = (x > 0.f) ? x : expm1f(x);
        x = c[j4 * 4 + 2]; v.z = (x > 0.f) ? x : expm1f(x);
        x = c[j4 * 4 + 3]; v.w = (x > 0.f) ? x : expm1f(x);
        outp[j4] = v;
    }
}

// --------------------- fused MLP: relu([ctx|nf] @ W1 + b1) @ W2 + b2, relu
// 512 threads (16 warps/SM), tile 128 nodes x 128 cols, 4x8 microtile.
// Weights split into half-width arrays (Wa: cols [8t..8t+3], Wb: cols [8t+4..8t+7])
// so every LDS.128 phase is bank-conflict-free. A-chunk stored transposed so the
// 4 microtile rows come from ONE LDS.128 (broadcast across tx).
// Smem floats:
//   W1a 10240 | W1b 10240 | W2a 8192 | W2b 8192 | AsT 16*132 | Hs 128*132 | b1s/b2s 256
// total 56128 floats = 224512 B, 1 block/SM.
__global__ __launch_bounds__(512, 1)
void mlp_kernel(const float4* __restrict__ nf4,
                const float* __restrict__ W1, const float* __restrict__ b1,
                const float* __restrict__ W2, const float* __restrict__ b2,
                float* __restrict__ out) {
    extern __shared__ float sm[];
    float* W1a = sm;                         // 160*64
    float* W1b = W1a + 10240;                // 160*64
    float* W2a = W1b + 10240;                // 128*64
    float* W2b = W2a + 8192;                 // 128*64
    float* AsT = W2b + 8192;                 // [KC][132]
    float* Hs  = AsT + KC * 132;             // [128][132]
    float* b1s = Hs + 128 * 132;             // 128
    float* b2s = b1s + 128;                  // 128

    const int tid = threadIdx.x;
    const int tx = tid & 15;                 // col group: cols tx*8 .. tx*8+7
    const int ty = tid >> 4;                 // row group: rows ty*4 .. ty*4+3
    const int node0 = blockIdx.x * TM;

    {   // stage weights, de-interleaved into half arrays
        const float4* w1v = reinterpret_cast<const float4*>(W1);
        float4* a1 = reinterpret_cast<float4*>(W1a);
        float4* bb1 = reinterpret_cast<float4*>(W1b);
#pragma unroll
        for (int i = 0; i < 10; i++) {
            int f = tid + i * 512;           // f = r*32 + c4, r<160, c4<32
            float4 v = w1v[f];
            int r = f >> 5, c4 = f & 31;
            if (c4 & 1) bb1[r * 16 + (c4 >> 1)] = v;
            else        a1[r * 16 + (c4 >> 1)] = v;
        }
        const float4* w2v = reinterpret_cast<const float4*>(W2);
        float4* a2 = reinterpret_cast<float4*>(W2a);
        float4* bb2 = reinterpret_cast<float4*>(W2b);
#pragma unroll
        for (int i = 0; i < 8; i++) {
            int f = tid + i * 512;
            float4 v = w2v[f];
            int r = f >> 5, c4 = f & 31;
            if (c4 & 1) bb2[r * 16 + (c4 >> 1)] = v;
            else        a2[r * 16 + (c4 >> 1)] = v;
        }
        if (tid < 128) b1s[tid] = b1[tid];
        else if (tid < 256) b2s[tid - 128] = b2[tid - 128];
    }

    float acc[4][8];
#pragma unroll
    for (int i = 0; i < 4; i++)
#pragma unroll
        for (int j = 0; j < 8; j++) acc[i][j] = 0.f;

    const float4* ctx4 = reinterpret_cast<const float4*>(g_ctx);
    const float4* w1av = reinterpret_cast<const float4*>(W1a);
    const float4* w1bv = reinterpret_cast<const float4*>(W1b);

    for (int kc = 0; kc < 10; kc++) {        // K = 160 = 10 chunks of 16
        __syncthreads();                     // AsT reuse fence (covers staging on kc=0)
        {   // stage A-chunk transposed: AsT[k][m]; 512 threads = 128 rows * 4 quads
            int m = tid >> 2, q = tid & 3;
            int node = node0 + m;
            if (node >= N_NODES) node = N_NODES - 1;   // clamp loads; stores guarded
            int k = kc * KC + q * 4;
            float4 v = (k < EDGE_HID) ? ctx4[node * 8 + (k >> 2)]
                                      : nf4[node * 32 + ((k - EDGE_HID) >> 2)];
            float* p = AsT + (q * 4) * 132 + m;
            p[0]       = v.x;
            p[132]     = v.y;
            p[264]     = v.z;
            p[396]     = v.w;
        }
        __syncthreads();
#pragma unroll
        for (int kk = 0; kk < KC; kk++) {
            int kg = kc * KC + kk;
            float4 av = *reinterpret_cast<const float4*>(&AsT[kk * 132 + ty * 4]);
            float a[4] = {av.x, av.y, av.z, av.w};
            float4 bl = w1av[kg * 16 + tx];
            float4 bh = w1bv[kg * 16 + tx];
            float b[8] = {bl.x, bl.y, bl.z, bl.w, bh.x, bh.y, bh.z, bh.w};
#pragma unroll
            for (int i = 0; i < 4; i++)
#pragma unroll
                for (int j = 0; j < 8; j++) acc[i][j] = fmaf(a[i], b[j], acc[i][j]);
        }
    }

    // epilogue 1: bias + relu -> Hs[row][col]
    {
        float bb[8];
#pragma unroll
        for (int j = 0; j < 8; j++) bb[j] = b1s[tx * 8 + j];
#pragma unroll
        for (int i = 0; i < 4; i++) {
            float4 v0, v1;
            v0.x = fmaxf(acc[i][0] + bb[0], 0.f);
            v0.y = fmaxf(acc[i][1] + bb[1], 0.f);
            v0.z = fmaxf(acc[i][2] + bb[2], 0.f);
            v0.w = fmaxf(acc[i][3] + bb[3], 0.f);
            v1.x = fmaxf(acc[i][4] + bb[4], 0.f);
            v1.y = fmaxf(acc[i][5] + bb[5], 0.f);
            v1.z = fmaxf(acc[i][6] + bb[6], 0.f);
            v1.w = fmaxf(acc[i][7] + bb[7], 0.f);
            float* hp = &Hs[(ty * 4 + i) * 132 + tx * 8];
            reinterpret_cast<float4*>(hp)[0] = v0;
            reinterpret_cast<float4*>(hp)[1] = v1;
        }
    }
    __syncthreads();

    // GEMM2: out = relu(H @ W2 + b2)
#pragma unroll
    for (int i = 0; i < 4; i++)
#pragma unroll
        for (int j = 0; j < 8; j++) acc[i][j] = 0.f;

    const float4* w2av = reinterpret_cast<const float4*>(W2a);
    const float4* w2bv = reinterpret_cast<const float4*>(W2b);
#pragma unroll 8
    for (int k = 0; k < 128; k++) {
        float a[4];
#pragma unroll
        for (int i = 0; i < 4; i++) a[i] = Hs[(ty * 4 + i) * 132 + k];  // broadcast
        float4 bl = w2av[k * 16 + tx];
        float4 bh = w2bv[k * 16 + tx];
        float b[8] = {bl.x, bl.y, bl.z, bl.w, bh.x, bh.y, bh.z, bh.w};
#pragma unroll
        for (int i = 0; i < 4; i++)
#pragma unroll
            for (int j = 0; j < 8; j++) acc[i][j] = fmaf(a[i], b[j], acc[i][j]);
    }

    {
        float bb[8];
#pragma unroll
        for (int j = 0; j < 8; j++) bb[j] = b2s[tx * 8 + j];
        int rem = N_NODES - node0;
#pragma unroll
        for (int i = 0; i < 4; i++) {
            int m = ty * 4 + i;
            if (m < rem) {
                float4 v0, v1;
                v0.x = fmaxf(acc[i][0] + bb[0], 0.f);
                v0.y = fmaxf(acc[i][1] + bb[1], 0.f);
                v0.z = fmaxf(acc[i][2] + bb[2], 0.f);
                v0.w = fmaxf(acc[i][3] + bb[3], 0.f);
                v1.x = fmaxf(acc[i][4] + bb[4], 0.f);
                v1.y = fmaxf(acc[i][5] + bb[5], 0.f);
                v1.z = fmaxf(acc[i][6] + bb[6], 0.f);
                v1.w = fmaxf(acc[i][7] + bb[7], 0.f);
                float* op = out + (node0 + m) * 128 + tx * 8;
                reinterpret_cast<float4*>(op)[0] = v0;
                reinterpret_cast<float4*>(op)[1] = v1;
            }
        }
    }
}

extern "C" void kernel_launch(void* const* d_in, const int* in_sizes, int n_in,
                              void* d_out, int out_size) {
    const float* edge_logits = (const float*)d_in[0];
    const float* edge_feats  = (const float*)d_in[1];
    const float* node_feats  = (const float*)d_in[2];
    const int*   dst         = (const int*)d_in[3];
    const float* W_et        = (const float*)d_in[4];
    const float* b_et        = (const float*)d_in[5];
    const float* W1          = (const float*)d_in[6];
    const float* b1          = (const float*)d_in[7];
    const float* W2          = (const float*)d_in[8];
    const float* b2          = (const float*)d_in[9];
    float* out = (float*)d_out;

    cudaFuncSetAttribute(mlp_kernel, cudaFuncAttributeMaxDynamicSharedMemorySize, 224512);

    zero_kernel<<<1024, 256>>>();
    edge_kernel<<<(N_EDGES * 4) / 256, 256>>>(edge_logits,
                                              (const float4*)edge_feats, dst);
    ctx_kernel<<<(N_NODES + 255) / 256, 256>>>(W_et, b_et);
    mlp_kernel<<<(N_NODES + TM - 1) / TM, 512, 224512>>>(
        (const float4*)node_feats, W1, b1, W2, b2, out);
    (void)in_sizes; (void)n_in; (void)out_size;
}